// round 2
// baseline (speedup 1.0000x reference)
#include <cuda_runtime.h>

typedef unsigned long long u64;

// ---------- packed f32x2 helpers (sm_103a has FFMA2 only via PTX) ----------
__device__ __forceinline__ u64 pack2(float lo, float hi){
    u64 r; asm("mov.b64 %0, {%1,%2};" : "=l"(r) : "f"(lo), "f"(hi)); return r;
}
__device__ __forceinline__ void unpack2(u64 v, float &lo, float &hi){
    asm("mov.b64 {%0,%1}, %2;" : "=f"(lo), "=f"(hi) : "l"(v));
}
__device__ __forceinline__ u64 mul2(u64 a, u64 b){
    u64 r; asm("mul.rn.f32x2 %0, %1, %2;" : "=l"(r) : "l"(a), "l"(b)); return r;
}
__device__ __forceinline__ void fma2(u64 &d, u64 a, u64 b){
    asm("fma.rn.f32x2 %0, %1, %2, %0;" : "+l"(d) : "l"(a), "l"(b));
}

// ---------- symmetrized coefficient tables (written by prep each launch) ----
// Monomial order must match the main-kernel triangular loops exactly.
__device__ u64 g_C1[9 * 4];      // deg-1: 9 monos x 4 cols  (b10 s0 | b11 p0..2)
__device__ u64 g_C2[45 * 8];     // deg-2: 45 monos x 8 cols (b20 s0,s1 | b21 s*3+p)
__device__ u64 g_C3[165 * 12];   // deg-3: 165 monos x 12 cols (b30 s0..2 | b31 s*3+p)

__device__ __forceinline__ float fetch3(const float* __restrict__ b30,
                                        const float* __restrict__ b31,
                                        int i, int j, int k, int c){
    int base = ((i * 9 + j) * 9 + k) * 3;         // b30: (9,9,9,3,1); b31: (9,9,9,3,3)
    if (c < 3) return b30[base + c];
    return b31[base * 3 + (c - 3)];
}

__global__ void prep_kernel(const float* __restrict__ b10, const float* __restrict__ b11,
                            const float* __restrict__ b20, const float* __restrict__ b21,
                            const float* __restrict__ b30, const float* __restrict__ b31){
    int tid = blockIdx.x * blockDim.x + threadIdx.x;

    // ---- deg-1: tasks [0, 36) ----
    if (tid < 36){
        int a = tid >> 2, c = tid & 3;
        float v = (c == 0) ? b10[a] : b11[a * 3 + c - 1];
        g_C1[tid] = pack2(v, v);
    }

    // ---- deg-2: tasks [64, 64+360) ----
    int t2 = tid - 64;
    if (t2 >= 0 && t2 < 45 * 8){
        int mono = t2 >> 3, c = t2 & 7;
        int a = 0, rem = mono;
        while (rem >= 9 - a){ rem -= 9 - a; a++; }
        int b = a + rem;                            // a <= b
        float v;
        if (c < 2){                                 // b20: (9,9,2,1)
            v = b20[(a * 9 + b) * 2 + c];
            if (a != b) v += b20[(b * 9 + a) * 2 + c];
        } else {                                    // b21: (9,9,2,3); c-2 = s*3+p
            int sp = c - 2;
            v = b21[(a * 9 + b) * 6 + sp];
            if (a != b) v += b21[(b * 9 + a) * 6 + sp];
        }
        g_C2[t2] = pack2(v, v);
    }

    // ---- deg-3: tasks [448, 448+1980) ----
    int t3 = tid - 448;
    if (t3 >= 0 && t3 < 165 * 12){
        int mono = t3 / 12, c = t3 % 12;
        int a = 0, rem = mono;
        while (true){ int cnt = (9 - a) * (10 - a) / 2; if (rem < cnt) break; rem -= cnt; a++; }
        int b = a;
        while (rem >= 9 - b){ rem -= 9 - b; b++; }
        int k = b + rem;                            // a <= b <= k
        float v = fetch3(b30, b31, a, b, k, c);
        if (a == b && b == k){
            // single permutation
        } else if (a == b){                         // (a,a,k): 3 perms
            v += fetch3(b30, b31, a, k, b, c) + fetch3(b30, b31, k, a, b, c);
        } else if (b == k){                         // (a,b,b): 3 perms
            v += fetch3(b30, b31, b, a, k, c) + fetch3(b30, b31, b, k, a, c);
        } else {                                    // all distinct: 6 perms
            v += fetch3(b30, b31, a, k, b, c) + fetch3(b30, b31, b, a, k, c)
               + fetch3(b30, b31, b, k, a, c) + fetch3(b30, b31, k, a, b, c)
               + fetch3(b30, b31, k, b, a, c);
        }
        g_C3[t3] = pack2(v, v);
    }
}

// ---------- main kernel: 1 block = 1 node, 64 threads x 2 channels ----------
__global__ void __launch_bounds__(64) mace_kernel(
    const float* __restrict__ nf, const int* __restrict__ species,
    const float* __restrict__ w10, const float* __restrict__ w11,
    const float* __restrict__ w20, const float* __restrict__ w21,
    const float* __restrict__ w30, const float* __restrict__ w31,
    float* __restrict__ out)
{
    __shared__ u64 sC1[9 * 4];
    __shared__ u64 sC2[45 * 8];
    __shared__ u64 sC3[165 * 12];
    __shared__ float sf[1152];
    __shared__ u64 sx[9 * 64];      // [component][thread] -> conflict-free LDS.64

    const int n = blockIdx.x;
    const int t = threadIdx.x;

    for (int i = t; i < 36;   i += 64) sC1[i] = g_C1[i];
    for (int i = t; i < 360;  i += 64) sC2[i] = g_C2[i];
    for (int i = t; i < 1980; i += 64) sC3[i] = g_C3[i];
    const float* nfp = nf + (size_t)n * 1152;
    for (int i = t; i < 1152; i += 64) sf[i] = nfp[i];
    __syncthreads();

    // Gather this thread's two channels (m0, m0+1) into packed x components.
    // node_feats layout: [0,128)=l0, [128,512)=l1 (mul-major, dim 3), [512,1152)=l2 (dim 5)
    const int m0 = t * 2;
    sx[0 * 64 + t] = pack2(sf[m0], sf[m0 + 1]);
    #pragma unroll
    for (int j = 0; j < 3; j++)
        sx[(1 + j) * 64 + t] = pack2(sf[128 + m0 * 3 + j], sf[128 + m0 * 3 + 3 + j]);
    #pragma unroll
    for (int j = 0; j < 5; j++)
        sx[(4 + j) * 64 + t] = pack2(sf[512 + m0 * 5 + j], sf[512 + m0 * 5 + 5 + j]);
    // sx[t] written+read only by thread t -> no extra sync needed.

    // Moment accumulators M[0..23]:
    //  [0]=b10(s0), [1..3]=b11(p), [4..5]=b20(s), [6..11]=b21(s*3+p),
    //  [12..14]=b30(s), [15..23]=b31(s*3+p)
    u64 M[24];
    #pragma unroll
    for (int i = 0; i < 24; i++) M[i] = 0ull;   // bit pattern of {0.f,0.f}

    const u64* c2p = sC2;
    const u64* c3p = sC3;
    for (int a = 0; a < 9; a++){
        u64 xa = sx[a * 64 + t];
        #pragma unroll
        for (int c = 0; c < 4; c++) fma2(M[c], sC1[a * 4 + c], xa);
        for (int b = a; b < 9; b++){
            u64 xb  = sx[b * 64 + t];
            u64 pab = mul2(xa, xb);
            #pragma unroll
            for (int c = 0; c < 8; c++) fma2(M[4 + c], c2p[c], pab);
            c2p += 8;
            for (int k = b; k < 9; k++){
                u64 p3 = mul2(pab, sx[k * 64 + t]);
                #pragma unroll
                for (int c = 0; c < 12; c++) fma2(M[12 + c], c3p[c], p3);
                c3p += 12;
            }
        }
    }

    // ---- combine with per-(species, channel) weights ----
    const int sp = species[n];
    // w10/w11: (10,1,128)  w20/w21: (10,2,128)  w30/w31: (10,3,128); m0 even -> 8B aligned
    u64 o0 = mul2(*(const u64*)(w10 + sp * 128 + m0), M[0]);
    fma2(o0, *(const u64*)(w20 + sp * 256 +   0 + m0), M[4]);
    fma2(o0, *(const u64*)(w20 + sp * 256 + 128 + m0), M[5]);
    fma2(o0, *(const u64*)(w30 + sp * 384 +   0 + m0), M[12]);
    fma2(o0, *(const u64*)(w30 + sp * 384 + 128 + m0), M[13]);
    fma2(o0, *(const u64*)(w30 + sp * 384 + 256 + m0), M[14]);

    u64 w11v  = *(const u64*)(w11 + sp * 128 + m0);
    u64 w21s0 = *(const u64*)(w21 + sp * 256 +   0 + m0);
    u64 w21s1 = *(const u64*)(w21 + sp * 256 + 128 + m0);
    u64 w31s0 = *(const u64*)(w31 + sp * 384 +   0 + m0);
    u64 w31s1 = *(const u64*)(w31 + sp * 384 + 128 + m0);
    u64 w31s2 = *(const u64*)(w31 + sp * 384 + 256 + m0);

    float* outp = out + (size_t)n * 512;
    {
        float lo, hi; unpack2(o0, lo, hi);
        *(float2*)(outp + m0) = make_float2(lo, hi);     // out slice 0: [0,128)
    }
    #pragma unroll
    for (int p = 0; p < 3; p++){
        u64 o = mul2(w11v, M[1 + p]);
        fma2(o, w21s0, M[6 + p]);
        fma2(o, w21s1, M[9 + p]);
        fma2(o, w31s0, M[15 + p]);
        fma2(o, w31s1, M[18 + p]);
        fma2(o, w31s2, M[21 + p]);
        float lo, hi; unpack2(o, lo, hi);
        outp[128 + m0 * 3 + p]     = lo;                 // out slice 1: [128,512)
        outp[128 + m0 * 3 + 3 + p] = hi;
    }
}

extern "C" void kernel_launch(void* const* d_in, const int* in_sizes, int n_in,
                              void* d_out, int out_size){
    // metadata order is INTERLEAVED (b_i, w_i) pairs — setup_inputs() inserts
    // names_b[i] then names_w[i] inside the same loop iteration.
    const float* nf      = (const float*)d_in[0];
    const int*   species = (const int*)  d_in[1];
    const float* b10 = (const float*)d_in[2];
    const float* w10 = (const float*)d_in[3];
    const float* b11 = (const float*)d_in[4];
    const float* w11 = (const float*)d_in[5];
    const float* b20 = (const float*)d_in[6];
    const float* w20 = (const float*)d_in[7];
    const float* b21 = (const float*)d_in[8];
    const float* w21 = (const float*)d_in[9];
    const float* b30 = (const float*)d_in[10];
    const float* w30 = (const float*)d_in[11];
    const float* b31 = (const float*)d_in[12];
    const float* w31 = (const float*)d_in[13];

    const int n_nodes = in_sizes[1];   // species element count

    // Symmetrize bases (tasks padded to [0,36) ∪ [64,424) ∪ [448,2428))
    prep_kernel<<<19, 128>>>(b10, b11, b20, b21, b30, b31);
    // One block per node, 64 threads x 2 packed channels
    mace_kernel<<<n_nodes, 64>>>(nf, species, w10, w11, w20, w21, w30, w31,
                                 (float*)d_out);
}

// round 3
// speedup vs baseline: 1.3298x; 1.3298x over previous
#include <cuda_runtime.h>

typedef unsigned long long u64;

// ---------- packed f32x2 helpers (sm_103a FFMA2 only via PTX) ----------
__device__ __forceinline__ u64 pack2(float lo, float hi){
    u64 r; asm("mov.b64 %0, {%1,%2};" : "=l"(r) : "f"(lo), "f"(hi)); return r;
}
__device__ __forceinline__ void unpack2(u64 v, float &lo, float &hi){
    asm("mov.b64 {%0,%1}, %2;" : "=f"(lo), "=f"(hi) : "l"(v));
}
__device__ __forceinline__ u64 mul2(u64 a, u64 b){
    u64 r; asm("mul.rn.f32x2 %0, %1, %2;" : "=l"(r) : "l"(a), "l"(b)); return r;
}
__device__ __forceinline__ void fma2(u64 &d, u64 a, u64 b){
    asm("fma.rn.f32x2 %0, %1, %2, %0;" : "+l"(d) : "l"(a), "l"(b));
}

// ---------- symmetrized coefficient tables (written by prep each launch) ----
// Duplicated {c,c} pairs; row strides are multiples of 16B for LDS.128.
__device__ __align__(16) u64 g_C1[9 * 4];      // deg-1: 9 monos x 4 cols
__device__ __align__(16) u64 g_C2[45 * 8];     // deg-2: 45 monos x 8 cols
__device__ __align__(16) u64 g_C3[165 * 12];   // deg-3: 165 monos x 12 cols

__device__ __forceinline__ float fetch3(const float* __restrict__ b30,
                                        const float* __restrict__ b31,
                                        int i, int j, int k, int c){
    int base = ((i * 9 + j) * 9 + k) * 3;         // b30: (9,9,9,3,1); b31: (9,9,9,3,3)
    if (c < 3) return b30[base + c];
    return b31[base * 3 + (c - 3)];
}

__global__ void prep_kernel(const float* __restrict__ b10, const float* __restrict__ b11,
                            const float* __restrict__ b20, const float* __restrict__ b21,
                            const float* __restrict__ b30, const float* __restrict__ b31){
    int tid = blockIdx.x * blockDim.x + threadIdx.x;

    // ---- deg-1: tasks [0, 36) ----
    if (tid < 36){
        int a = tid >> 2, c = tid & 3;
        float v = (c == 0) ? b10[a] : b11[a * 3 + c - 1];
        g_C1[tid] = pack2(v, v);
    }

    // ---- deg-2: tasks [64, 64+360) ----
    int t2 = tid - 64;
    if (t2 >= 0 && t2 < 45 * 8){
        int mono = t2 >> 3, c = t2 & 7;
        int a = 0, rem = mono;
        while (rem >= 9 - a){ rem -= 9 - a; a++; }
        int b = a + rem;                            // a <= b
        float v;
        if (c < 2){                                 // b20: (9,9,2,1)
            v = b20[(a * 9 + b) * 2 + c];
            if (a != b) v += b20[(b * 9 + a) * 2 + c];
        } else {                                    // b21: (9,9,2,3); c-2 = s*3+p
            int sp = c - 2;
            v = b21[(a * 9 + b) * 6 + sp];
            if (a != b) v += b21[(b * 9 + a) * 6 + sp];
        }
        g_C2[t2] = pack2(v, v);
    }

    // ---- deg-3: tasks [448, 448+1980) ----
    int t3 = tid - 448;
    if (t3 >= 0 && t3 < 165 * 12){
        int mono = t3 / 12, c = t3 % 12;
        int a = 0, rem = mono;
        while (true){ int cnt = (9 - a) * (10 - a) / 2; if (rem < cnt) break; rem -= cnt; a++; }
        int b = a;
        while (rem >= 9 - b){ rem -= 9 - b; b++; }
        int k = b + rem;                            // a <= b <= k
        float v = fetch3(b30, b31, a, b, k, c);
        if (a == b && b == k){
            // single permutation
        } else if (a == b){                         // (a,a,k): 3 perms
            v += fetch3(b30, b31, a, k, b, c) + fetch3(b30, b31, k, a, b, c);
        } else if (b == k){                         // (a,b,b): 3 perms
            v += fetch3(b30, b31, b, a, k, c) + fetch3(b30, b31, b, k, a, c);
        } else {                                    // all distinct: 6 perms
            v += fetch3(b30, b31, a, k, b, c) + fetch3(b30, b31, b, a, k, c)
               + fetch3(b30, b31, b, k, a, c) + fetch3(b30, b31, k, a, b, c)
               + fetch3(b30, b31, k, b, a, c);
        }
        g_C3[t3] = pack2(v, v);
    }
}

// ---------- main kernel: 1 block = 2 nodes, 128 threads, 2 channels/thread --
__global__ void __launch_bounds__(128, 4) mace_kernel(
    const float* __restrict__ nf, const int* __restrict__ species,
    const float* __restrict__ w10, const float* __restrict__ w11,
    const float* __restrict__ w20, const float* __restrict__ w21,
    const float* __restrict__ w30, const float* __restrict__ w31,
    float* __restrict__ out)
{
    __shared__ __align__(16) u64 sC1[9 * 4];
    __shared__ __align__(16) u64 sC2[45 * 8];
    __shared__ __align__(16) u64 sC3[165 * 12];

    const int t = threadIdx.x;
    for (int i = t; i < 36;   i += 128) sC1[i] = g_C1[i];
    for (int i = t; i < 360;  i += 128) sC2[i] = g_C2[i];
    for (int i = t; i < 1980; i += 128) sC3[i] = g_C3[i];
    __syncthreads();

    const int node = blockIdx.x * 2 + (t >> 6);
    const int tl   = t & 63;
    const int m0   = tl * 2;                 // this thread's channel pair
    const float* nfp = nf + (size_t)node * 1152;

    // x components (2 channels packed) fully in registers.
    // layout: [0,128)=l0, [128,512)=l1 (mul-major dim3), [512,1152)=l2 (dim5)
    u64 x[9];
    {
        float2 v = *(const float2*)(nfp + m0);
        x[0] = pack2(v.x, v.y);
    }
    #pragma unroll
    for (int j = 0; j < 3; j++)
        x[1 + j] = pack2(nfp[128 + m0 * 3 + j], nfp[128 + m0 * 3 + 3 + j]);
    #pragma unroll
    for (int j = 0; j < 5; j++)
        x[4 + j] = pack2(nfp[512 + m0 * 5 + j], nfp[512 + m0 * 5 + 5 + j]);

    // Moment accumulators:
    //  [0]=b10(s0), [1..3]=b11(p), [4..5]=b20(s), [6..11]=b21(s*3+p),
    //  [12..14]=b30(s), [15..23]=b31(s*3+p)
    u64 M[24];
    #pragma unroll
    for (int i = 0; i < 24; i++) M[i] = 0ull;

    int i2 = 0, i3 = 0;                       // constant-folded by full unroll
    #pragma unroll
    for (int a = 0; a < 9; a++){
        #pragma unroll
        for (int c = 0; c < 2; c++){
            ulonglong2 cp = *(const ulonglong2*)(sC1 + a * 4 + 2 * c);
            fma2(M[2 * c],     cp.x, x[a]);
            fma2(M[2 * c + 1], cp.y, x[a]);
        }
        #pragma unroll
        for (int b = a; b < 9; b++){
            u64 pab = mul2(x[a], x[b]);
            #pragma unroll
            for (int c = 0; c < 4; c++){
                ulonglong2 cp = *(const ulonglong2*)(sC2 + i2 * 8 + 2 * c);
                fma2(M[4 + 2 * c],     cp.x, pab);
                fma2(M[4 + 2 * c + 1], cp.y, pab);
            }
            i2++;
            #pragma unroll
            for (int k = b; k < 9; k++){
                u64 p3 = mul2(pab, x[k]);
                #pragma unroll
                for (int c = 0; c < 6; c++){
                    ulonglong2 cp = *(const ulonglong2*)(sC3 + i3 * 12 + 2 * c);
                    fma2(M[12 + 2 * c],     cp.x, p3);
                    fma2(M[12 + 2 * c + 1], cp.y, p3);
                }
                i3++;
            }
        }
    }

    // ---- combine with per-(species, channel) weights ----
    const int sp = species[node];
    // w10/w11: (10,1,128)  w20/w21: (10,2,128)  w30/w31: (10,3,128); m0 even -> 8B aligned
    u64 o0 = mul2(*(const u64*)(w10 + sp * 128 + m0), M[0]);
    fma2(o0, *(const u64*)(w20 + sp * 256 +   0 + m0), M[4]);
    fma2(o0, *(const u64*)(w20 + sp * 256 + 128 + m0), M[5]);
    fma2(o0, *(const u64*)(w30 + sp * 384 +   0 + m0), M[12]);
    fma2(o0, *(const u64*)(w30 + sp * 384 + 128 + m0), M[13]);
    fma2(o0, *(const u64*)(w30 + sp * 384 + 256 + m0), M[14]);

    u64 w11v  = *(const u64*)(w11 + sp * 128 + m0);
    u64 w21s0 = *(const u64*)(w21 + sp * 256 +   0 + m0);
    u64 w21s1 = *(const u64*)(w21 + sp * 256 + 128 + m0);
    u64 w31s0 = *(const u64*)(w31 + sp * 384 +   0 + m0);
    u64 w31s1 = *(const u64*)(w31 + sp * 384 + 128 + m0);
    u64 w31s2 = *(const u64*)(w31 + sp * 384 + 256 + m0);

    float* outp = out + (size_t)node * 512;
    {
        float lo, hi; unpack2(o0, lo, hi);
        *(float2*)(outp + m0) = make_float2(lo, hi);     // out slice 0: [0,128)
    }
    #pragma unroll
    for (int p = 0; p < 3; p++){
        u64 o = mul2(w11v, M[1 + p]);
        fma2(o, w21s0, M[6 + p]);
        fma2(o, w21s1, M[9 + p]);
        fma2(o, w31s0, M[15 + p]);
        fma2(o, w31s1, M[18 + p]);
        fma2(o, w31s2, M[21 + p]);
        float lo, hi; unpack2(o, lo, hi);
        outp[128 + m0 * 3 + p]     = lo;                 // out slice 1: [128,512)
        outp[128 + m0 * 3 + 3 + p] = hi;
    }
}

extern "C" void kernel_launch(void* const* d_in, const int* in_sizes, int n_in,
                              void* d_out, int out_size){
    // metadata order is INTERLEAVED (b_i, w_i) pairs.
    const float* nf      = (const float*)d_in[0];
    const int*   species = (const int*)  d_in[1];
    const float* b10 = (const float*)d_in[2];
    const float* w10 = (const float*)d_in[3];
    const float* b11 = (const float*)d_in[4];
    const float* w11 = (const float*)d_in[5];
    const float* b20 = (const float*)d_in[6];
    const float* w20 = (const float*)d_in[7];
    const float* b21 = (const float*)d_in[8];
    const float* w21 = (const float*)d_in[9];
    const float* b30 = (const float*)d_in[10];
    const float* w30 = (const float*)d_in[11];
    const float* b31 = (const float*)d_in[12];
    const float* w31 = (const float*)d_in[13];

    const int n_nodes = in_sizes[1];   // species element count (2048, even)

    prep_kernel<<<19, 128>>>(b10, b11, b20, b21, b30, b31);
    mace_kernel<<<n_nodes / 2, 128>>>(nf, species, w10, w11, w20, w21, w30, w31,
                                      (float*)d_out);
}

// round 4
// speedup vs baseline: 1.3928x; 1.0474x over previous
#include <cuda_runtime.h>

typedef unsigned long long u64;

// ---------- packed f32x2 helpers (sm_103a FFMA2 only via PTX) ----------
__device__ __forceinline__ u64 pack2(float lo, float hi){
    u64 r; asm("mov.b64 %0, {%1,%2};" : "=l"(r) : "f"(lo), "f"(hi)); return r;
}
__device__ __forceinline__ void unpack2(u64 v, float &lo, float &hi){
    asm("mov.b64 {%0,%1}, %2;" : "=f"(lo), "=f"(hi) : "l"(v));
}
__device__ __forceinline__ u64 mul2(u64 a, u64 b){
    u64 r; asm("mul.rn.f32x2 %0, %1, %2;" : "=l"(r) : "l"(a), "l"(b)); return r;
}
__device__ __forceinline__ void fma2(u64 &d, u64 a, u64 b){
    asm("fma.rn.f32x2 %0, %1, %2, %0;" : "+l"(d) : "l"(a), "l"(b));
}

// ---------- symmetrized coefficient tables (written by prep each launch) ----
// Duplicated {c,c} pairs; row strides are multiples of 16B for LDS.128.
__device__ __align__(16) u64 g_C1[9 * 4];      // deg-1: 9 monos x 4 cols
__device__ __align__(16) u64 g_C2[45 * 8];     // deg-2: 45 monos x 8 cols
__device__ __align__(16) u64 g_C3[165 * 12];   // deg-3: 165 monos x 12 cols

__device__ __forceinline__ float fetch3(const float* __restrict__ b30,
                                        const float* __restrict__ b31,
                                        int i, int j, int k, int c){
    int base = ((i * 9 + j) * 9 + k) * 3;         // b30: (9,9,9,3,1); b31: (9,9,9,3,3)
    if (c < 3) return b30[base + c];
    return b31[base * 3 + (c - 3)];
}

__global__ void prep_kernel(const float* __restrict__ b10, const float* __restrict__ b11,
                            const float* __restrict__ b20, const float* __restrict__ b21,
                            const float* __restrict__ b30, const float* __restrict__ b31){
    int tid = blockIdx.x * blockDim.x + threadIdx.x;

    // ---- deg-1: tasks [0, 36) ----
    if (tid < 36){
        int a = tid >> 2, c = tid & 3;
        float v = (c == 0) ? b10[a] : b11[a * 3 + c - 1];
        g_C1[tid] = pack2(v, v);
    }

    // ---- deg-2: tasks [64, 64+360) ----
    int t2 = tid - 64;
    if (t2 >= 0 && t2 < 45 * 8){
        int mono = t2 >> 3, c = t2 & 7;
        int a = 0, rem = mono;
        while (rem >= 9 - a){ rem -= 9 - a; a++; }
        int b = a + rem;                            // a <= b
        float v;
        if (c < 2){                                 // b20: (9,9,2,1)
            v = b20[(a * 9 + b) * 2 + c];
            if (a != b) v += b20[(b * 9 + a) * 2 + c];
        } else {                                    // b21: (9,9,2,3); c-2 = s*3+p
            int sp = c - 2;
            v = b21[(a * 9 + b) * 6 + sp];
            if (a != b) v += b21[(b * 9 + a) * 6 + sp];
        }
        g_C2[t2] = pack2(v, v);
    }

    // ---- deg-3: tasks [448, 448+1980) ----
    int t3 = tid - 448;
    if (t3 >= 0 && t3 < 165 * 12){
        int mono = t3 / 12, c = t3 % 12;
        int a = 0, rem = mono;
        while (true){ int cnt = (9 - a) * (10 - a) / 2; if (rem < cnt) break; rem -= cnt; a++; }
        int b = a;
        while (rem >= 9 - b){ rem -= 9 - b; b++; }
        int k = b + rem;                            // a <= b <= k
        float v = fetch3(b30, b31, a, b, k, c);
        if (a == b && b == k){
            // single permutation
        } else if (a == b){                         // (a,a,k): 3 perms
            v += fetch3(b30, b31, a, k, b, c) + fetch3(b30, b31, k, a, b, c);
        } else if (b == k){                         // (a,b,b): 3 perms
            v += fetch3(b30, b31, b, a, k, c) + fetch3(b30, b31, b, k, a, c);
        } else {                                    // all distinct: 6 perms
            v += fetch3(b30, b31, a, k, b, c) + fetch3(b30, b31, b, a, k, c)
               + fetch3(b30, b31, b, k, a, c) + fetch3(b30, b31, k, a, b, c)
               + fetch3(b30, b31, k, b, a, c);
        }
        g_C3[t3] = pack2(v, v);
    }
}

// ---------- main kernel: 1 block = 2 nodes, 64 threads, 4 channels/thread ---
__global__ void __launch_bounds__(64, 6) mace_kernel(
    const float* __restrict__ nf, const int* __restrict__ species,
    const float* __restrict__ w10, const float* __restrict__ w11,
    const float* __restrict__ w20, const float* __restrict__ w21,
    const float* __restrict__ w30, const float* __restrict__ w31,
    float* __restrict__ out)
{
    __shared__ __align__(16) u64 sC1[9 * 4];
    __shared__ __align__(16) u64 sC2[45 * 8];
    __shared__ __align__(16) u64 sC3[165 * 12];

    const int t = threadIdx.x;
    for (int i = t; i < 36;   i += 64) sC1[i] = g_C1[i];
    for (int i = t; i < 360;  i += 64) sC2[i] = g_C2[i];
    for (int i = t; i < 1980; i += 64) sC3[i] = g_C3[i];
    __syncthreads();

    const int node = blockIdx.x * 2 + (t >> 5);
    const int tl   = t & 31;
    const int m0   = tl * 4;                 // channels m0..m0+3 (A pair, B pair)
    const float* nfp = nf + (size_t)node * 1152;

    // x components fully in registers.
    // layout: [0,128)=l0, [128,512)=l1 (mul-major dim3), [512,1152)=l2 (dim5)
    u64 xA[9], xB[9];
    {
        float4 v = *(const float4*)(nfp + m0);   // m0 % 4 == 0 -> 16B aligned
        xA[0] = pack2(v.x, v.y);
        xB[0] = pack2(v.z, v.w);
    }
    #pragma unroll
    for (int j = 0; j < 3; j++){
        xA[1 + j] = pack2(nfp[128 + m0 * 3 + j],      nfp[128 + m0 * 3 + 3 + j]);
        xB[1 + j] = pack2(nfp[128 + m0 * 3 + 6 + j],  nfp[128 + m0 * 3 + 9 + j]);
    }
    #pragma unroll
    for (int j = 0; j < 5; j++){
        xA[4 + j] = pack2(nfp[512 + m0 * 5 + j],      nfp[512 + m0 * 5 + 5 + j]);
        xB[4 + j] = pack2(nfp[512 + m0 * 5 + 10 + j], nfp[512 + m0 * 5 + 15 + j]);
    }

    // Moment accumulators (per channel-pair):
    //  [0]=b10(s0), [1..3]=b11(p), [4..5]=b20(s), [6..11]=b21(s*3+p),
    //  [12..14]=b30(s), [15..23]=b31(s*3+p)
    u64 MA[24], MB[24];
    #pragma unroll
    for (int i = 0; i < 24; i++){ MA[i] = 0ull; MB[i] = 0ull; }

    int i2 = 0, i3 = 0;                       // constant-folded by full unroll
    #pragma unroll
    for (int a = 0; a < 9; a++){
        #pragma unroll
        for (int c = 0; c < 2; c++){
            ulonglong2 cp = *(const ulonglong2*)(sC1 + a * 4 + 2 * c);
            fma2(MA[2 * c],     cp.x, xA[a]);  fma2(MB[2 * c],     cp.x, xB[a]);
            fma2(MA[2 * c + 1], cp.y, xA[a]);  fma2(MB[2 * c + 1], cp.y, xB[a]);
        }
        #pragma unroll
        for (int b = a; b < 9; b++){
            u64 pabA = mul2(xA[a], xA[b]);
            u64 pabB = mul2(xB[a], xB[b]);
            #pragma unroll
            for (int c = 0; c < 4; c++){
                ulonglong2 cp = *(const ulonglong2*)(sC2 + i2 * 8 + 2 * c);
                fma2(MA[4 + 2 * c],     cp.x, pabA);  fma2(MB[4 + 2 * c],     cp.x, pabB);
                fma2(MA[4 + 2 * c + 1], cp.y, pabA);  fma2(MB[4 + 2 * c + 1], cp.y, pabB);
            }
            i2++;
            #pragma unroll
            for (int k = b; k < 9; k++){
                u64 p3A = mul2(pabA, xA[k]);
                u64 p3B = mul2(pabB, xB[k]);
                #pragma unroll
                for (int c = 0; c < 6; c++){
                    ulonglong2 cp = *(const ulonglong2*)(sC3 + i3 * 12 + 2 * c);
                    fma2(MA[12 + 2 * c],     cp.x, p3A);  fma2(MB[12 + 2 * c],     cp.x, p3B);
                    fma2(MA[12 + 2 * c + 1], cp.y, p3A);  fma2(MB[12 + 2 * c + 1], cp.y, p3B);
                }
                i3++;
            }
        }
    }

    // ---- combine with per-(species, channel) weights ----
    const int sp = species[node];
    float* outp = out + (size_t)node * 512;

    // slice 0 ([0,128)): both pairs -> one float4 store
    float o0[4];
    #pragma unroll
    for (int h = 0; h < 2; h++){
        const int mc = m0 + 2 * h;
        u64* M = h ? MB : MA;
        u64 o = mul2(*(const u64*)(w10 + sp * 128 + mc), M[0]);
        fma2(o, *(const u64*)(w20 + sp * 256 +   0 + mc), M[4]);
        fma2(o, *(const u64*)(w20 + sp * 256 + 128 + mc), M[5]);
        fma2(o, *(const u64*)(w30 + sp * 384 +   0 + mc), M[12]);
        fma2(o, *(const u64*)(w30 + sp * 384 + 128 + mc), M[13]);
        fma2(o, *(const u64*)(w30 + sp * 384 + 256 + mc), M[14]);
        unpack2(o, o0[2 * h], o0[2 * h + 1]);
    }
    *(float4*)(outp + m0) = make_float4(o0[0], o0[1], o0[2], o0[3]);

    // slice 1 ([128,512)): dim-3 per channel
    #pragma unroll
    for (int h = 0; h < 2; h++){
        const int mc = m0 + 2 * h;
        u64* M = h ? MB : MA;
        u64 w11v  = *(const u64*)(w11 + sp * 128 + mc);
        u64 w21s0 = *(const u64*)(w21 + sp * 256 +   0 + mc);
        u64 w21s1 = *(const u64*)(w21 + sp * 256 + 128 + mc);
        u64 w31s0 = *(const u64*)(w31 + sp * 384 +   0 + mc);
        u64 w31s1 = *(const u64*)(w31 + sp * 384 + 128 + mc);
        u64 w31s2 = *(const u64*)(w31 + sp * 384 + 256 + mc);
        #pragma unroll
        for (int p = 0; p < 3; p++){
            u64 o = mul2(w11v, M[1 + p]);
            fma2(o, w21s0, M[6 + p]);
            fma2(o, w21s1, M[9 + p]);
            fma2(o, w31s0, M[15 + p]);
            fma2(o, w31s1, M[18 + p]);
            fma2(o, w31s2, M[21 + p]);
            float lo, hi; unpack2(o, lo, hi);
            outp[128 + mc * 3 + p]     = lo;
            outp[128 + mc * 3 + 3 + p] = hi;
        }
    }
}

extern "C" void kernel_launch(void* const* d_in, const int* in_sizes, int n_in,
                              void* d_out, int out_size){
    // metadata order is INTERLEAVED (b_i, w_i) pairs.
    const float* nf      = (const float*)d_in[0];
    const int*   species = (const int*)  d_in[1];
    const float* b10 = (const float*)d_in[2];
    const float* w10 = (const float*)d_in[3];
    const float* b11 = (const float*)d_in[4];
    const float* w11 = (const float*)d_in[5];
    const float* b20 = (const float*)d_in[6];
    const float* w20 = (const float*)d_in[7];
    const float* b21 = (const float*)d_in[8];
    const float* w21 = (const float*)d_in[9];
    const float* b30 = (const float*)d_in[10];
    const float* w30 = (const float*)d_in[11];
    const float* b31 = (const float*)d_in[12];
    const float* w31 = (const float*)d_in[13];

    const int n_nodes = in_sizes[1];   // species element count (2048, even)

    prep_kernel<<<19, 128>>>(b10, b11, b20, b21, b30, b31);
    // 1 block = 2 nodes, 32 threads/node, 4 channels/thread
    mace_kernel<<<n_nodes / 2, 64>>>(nf, species, w10, w11, w20, w21, w30, w31,
                                     (float*)d_out);
}